// round 11
// baseline (speedup 1.0000x reference)
#include <cuda_runtime.h>

#define CIN 16
#define DIN 64
#define HIN 96
#define WIN 96
#define DD 32
#define HH 48
#define WW 48
#define NVOX (DD*HH*WW)          /* 73728 */
#define RR 3
#define PD (DD+2*RR)             /* 38 */
#define PH (HH+2*RR)             /* 54 */
#define PW (WW+2*RR)             /* 54 */
#define FMS 64                   /* padded row stride (float4) for g_fm */

#define N_FF (4*NVOX)
#define N_FM (4*PD*PH*PW)
#define NGRP (NVOX/2)            /* 36864 voxel-pairs */

// Pooled features. g_ff: ((z*HH+y)*4+q)*WW + x. g_fm zero-padded by RR each
// side, row stride padded to 64 float4 (shift addressing, aligned rows).
__device__ float4 g_ff[(size_t)DD*HH*4*WW];
__device__ __align__(256) float4 g_fm[(size_t)PD*PH*4*FMS];

// ---------------------------------------------------------------------------
// Fused pooling (both tensors, one grid) + zeroing of the output buffer.
// ---------------------------------------------------------------------------
__global__ void pool_kernel(const float* __restrict__ ff_in,
                            const float* __restrict__ fm_in,
                            float* __restrict__ out) {
    int i = blockIdx.x * blockDim.x + threadIdx.x;
    if (i < 2 * NVOX) out[i] = 0.0f;             // init output (scatter target)
    if (i < N_FF) {
        int x = i % WW;
        int y = (i / WW) % HH;
        int z = (i / (WW * HH)) % DD;
        int q = i / NVOX;
        float s[4];
#pragma unroll
        for (int cc = 0; cc < 4; cc++) {
            int c = q * 4 + cc;
            const float* p = ff_in + (((size_t)c * DIN + 2 * z) * HIN + 2 * y) * WIN + 2 * x;
            float acc = 0.f;
#pragma unroll
            for (int dz = 0; dz < 2; dz++)
#pragma unroll
                for (int dy = 0; dy < 2; dy++) {
                    const float2 v = *(const float2*)(p + (size_t)dz * HIN * WIN + dy * WIN);
                    acc += v.x + v.y;
                }
            s[cc] = acc * 0.125f;
        }
        g_ff[((size_t)(z * HH + y) * 4 + q) * WW + x] = make_float4(s[0], s[1], s[2], s[3]);
    } else {
        int j = i - N_FF;
        if (j >= N_FM) return;
        int x = j % PW;
        int y = (j / PW) % PH;
        int z = (j / (PW * PH)) % PD;
        int q = j / (PD * PH * PW);
        int iz = z - RR, iy = y - RR, ix = x - RR;
        float s[4] = {0.f, 0.f, 0.f, 0.f};
        if (iz >= 0 && iz < DD && iy >= 0 && iy < HH && ix >= 0 && ix < WW) {
#pragma unroll
            for (int cc = 0; cc < 4; cc++) {
                int c = q * 4 + cc;
                const float* p = fm_in + (((size_t)c * DIN + 2 * iz) * HIN + 2 * iy) * WIN + 2 * ix;
                float acc = 0.f;
#pragma unroll
                for (int dz = 0; dz < 2; dz++)
#pragma unroll
                    for (int dy = 0; dy < 2; dy++) {
                        const float2 v = *(const float2*)(p + (size_t)dz * HIN * WIN + dy * WIN);
                        acc += v.x + v.y;
                    }
                s[cc] = acc * 0.125f;
            }
        }
        g_fm[((size_t)(z * PH + y) * 4 + q) * FMS + x] = make_float4(s[0], s[1], s[2], s[3]);
    }
}

// ---------------------------------------------------------------------------
// Top-5 (strict > keeps earliest window index on ties, matching lax.top_k)
// ---------------------------------------------------------------------------
struct Top5 { float v0, v1, v2, v3, v4; int p0, p1, p2, p3, p4; };

__device__ __forceinline__ void top5_init(Top5& t) {
    t.v0 = t.v1 = t.v2 = t.v3 = t.v4 = -1e30f;
    t.p0 = t.p1 = t.p2 = t.p3 = t.p4 = 0;
}

__device__ __forceinline__ void top5_ins(Top5& t, float c, int p) {
    if (c > t.v4) {
        t.v4 = c; t.p4 = p;
        if (t.v4 > t.v3) { float f = t.v4; t.v4 = t.v3; t.v3 = f; int u = t.p4; t.p4 = t.p3; t.p3 = u; }
        if (t.v3 > t.v2) { float f = t.v3; t.v3 = t.v2; t.v2 = f; int u = t.p3; t.p3 = t.p2; t.p2 = u; }
        if (t.v2 > t.v1) { float f = t.v2; t.v2 = t.v1; t.v1 = f; int u = t.p2; t.p2 = t.p1; t.p1 = u; }
        if (t.v1 > t.v0) { float f = t.v1; t.v1 = t.v0; t.v0 = f; int u = t.p1; t.p1 = t.p0; t.p0 = u; }
    }
}

// ---------------------------------------------------------------------------
// One fm z-slab (7x7 in-plane window) against up to two outputs.
// Channel accumulation is q-sequential (c = 0..15 in order, matching the
// reference summation; only 4 live m registers).
// ---------------------------------------------------------------------------
template <bool DA, bool DB>
__device__ __forceinline__ void run_slice(
    int zslab, int y, int x, int pA, int pB,
    const float4& A0, const float4& A1, const float4& A2, const float4& A3,
    const float4& B0, const float4& B1, const float4& B2, const float4& B3,
    Top5& tA, Top5& tB)
{
    for (int py = 0; py < 7; py++) {
        const float4* __restrict__ mb =
            &g_fm[((size_t)(zslab * PH + (y + py)) * 4) * FMS + x];
        const float4* __restrict__ mb0 = mb;
        const float4* __restrict__ mb1 = mb + FMS;
        const float4* __restrict__ mb2 = mb + 2 * FMS;
        const float4* __restrict__ mb3 = mb + 3 * FMS;
        const int rA = pA + py * 7;
        const int rB = pB + py * 7;
#pragma unroll
        for (int px = 0; px < 7; px++) {
            float4 m0 = mb0[px];
            float4 m1 = mb1[px];
            float4 m2 = mb2[px];
            float4 m3 = mb3[px];
            if (DA) {
                float c = A0.x * m0.x;
                c = fmaf(A0.y, m0.y, c); c = fmaf(A0.z, m0.z, c); c = fmaf(A0.w, m0.w, c);
                c = fmaf(A1.x, m1.x, c); c = fmaf(A1.y, m1.y, c);
                c = fmaf(A1.z, m1.z, c); c = fmaf(A1.w, m1.w, c);
                c = fmaf(A2.x, m2.x, c); c = fmaf(A2.y, m2.y, c);
                c = fmaf(A2.z, m2.z, c); c = fmaf(A2.w, m2.w, c);
                c = fmaf(A3.x, m3.x, c); c = fmaf(A3.y, m3.y, c);
                c = fmaf(A3.z, m3.z, c); c = fmaf(A3.w, m3.w, c);
                top5_ins(tA, c, rA + px);
            }
            if (DB) {
                float c = B0.x * m0.x;
                c = fmaf(B0.y, m0.y, c); c = fmaf(B0.z, m0.z, c); c = fmaf(B0.w, m0.w, c);
                c = fmaf(B1.x, m1.x, c); c = fmaf(B1.y, m1.y, c);
                c = fmaf(B1.z, m1.z, c); c = fmaf(B1.w, m1.w, c);
                c = fmaf(B2.x, m2.x, c); c = fmaf(B2.y, m2.y, c);
                c = fmaf(B2.z, m2.z, c); c = fmaf(B2.w, m2.w, c);
                c = fmaf(B3.x, m3.x, c); c = fmaf(B3.y, m3.y, c);
                c = fmaf(B3.z, m3.z, c); c = fmaf(B3.w, m3.w, c);
                top5_ins(tB, c, rB + px);
            }
        }
    }
}

// ---------------------------------------------------------------------------
// scatter one top-k winner into both output levels
// ---------------------------------------------------------------------------
__device__ __forceinline__ void scatter_one(float* __restrict__ out,
                                            int z, int y, int x,
                                            float v, int pj) {
    const float sc[4] = {1.0f, 0.5f, 0.25f, 0.125f};
    int oz = pj / 49 - 3;
    int oy = (pj / 7) % 7 - 3;
    int ox = pj % 7 - 3;

    // level 0: integer displacement, single unit-weight corner
    {
        int tz = min(max(z + oz, 0), DD - 1);
        int ty = min(max(y + oy, 0), HH - 1);
        int tx = min(max(x + ox, 0), WW - 1);
        atomicAdd(&out[(tz * HH + ty) * WW + tx], v);
    }
    // level 1: displacement * 0.5, trilinear splat
    {
        int fz = oz >> 1, fy = oy >> 1, fx = ox >> 1;   // floor(o/2)
        int ez = oz & 1, ey = oy & 1, ex = ox & 1;      // odd -> two corners
        float wv = v * sc[ez + ey + ex];
        float* out1 = out + NVOX;
#pragma unroll
        for (int cz = 0; cz < 2; cz++) {
            if (cz > ez) break;
            int tz = min(max(z + fz + cz, 0), DD - 1);
#pragma unroll
            for (int cy = 0; cy < 2; cy++) {
                if (cy > ey) break;
                int ty = min(max(y + fy + cy, 0), HH - 1);
#pragma unroll
                for (int cx = 0; cx < 2; cx++) {
                    if (cx > ex) break;
                    int tx = min(max(x + fx + cx, 0), WW - 1);
                    atomicAdd(&out1[(tz * HH + ty) * WW + tx], wv);
                }
            }
        }
    }
}

// merge 4 partial top-5 lists (20 smem entries) -> global top-5, then scatter.
// Tie-break: equal values -> smaller flat window index p (matches lax.top_k;
// partial lists cover disjoint p-ranges so cross-list ties resolve by p).
__device__ __forceinline__ void merge_scatter(const float* __restrict__ sv,
                                              const int* __restrict__ si,
                                              float* __restrict__ out,
                                              int z, int y, int x) {
    unsigned used = 0;
#pragma unroll
    for (int k = 0; k < 5; k++) {
        float best = -3e38f;
        int bestp = 0x7fffffff;
        int bi = 0;
        for (int i = 0; i < 20; i++) {
            if (used & (1u << i)) continue;
            float v = sv[i];
            int p = si[i];
            if (v > best || (v == best && p < bestp)) { best = v; bestp = p; bi = i; }
        }
        used |= 1u << bi;
        scatter_one(out, z, y, x, best, bestp);
    }
}

// ---------------------------------------------------------------------------
// Correlation + top-5 + scatter with ZB=2 z-sharing.
// A voxel-pair (z, z+1) at (y, x) is handled by the same lane of the block's
// 4 warps; warp w owns fm slabs {2w, 2w+1} of the pair's 8-slab span.
// Each loaded m vector feeds the dot for output z (slab index pza < 7) and
// output z+1 (pza >= 1): per-output load traffic is halved vs one-voxel-per-
// thread.  Template booleans make the single-dot edge slabs (pza = 0, 7)
// separate warp-uniform code paths (no dead predicated FMAs).
// __launch_bounds__(128,7) caps regs at ~72 so 28 warps/SM stay resident
// (R8's 98-reg variant collapsed to 21% occupancy; R9 showed 28 warps
// sustain >50% issue).  Lanes map to 32 consecutive voxel-groups -> x-
// consecutive, fully coalesced 512B row loads.
// ---------------------------------------------------------------------------
__global__ void __launch_bounds__(128, 7) corr_scatter_kernel(float* __restrict__ out) {
    __shared__ float sv[2][32][20];
    __shared__ int   si[2][32][20];

    const int lane = threadIdx.x & 31;
    const int sub  = threadIdx.x >> 5;           // 0..3, warp-uniform
    const int grp  = blockIdx.x * 32 + lane;     // exact grid: no guard
    const int x = grp % WW;
    const int y = (grp / WW) % HH;
    const int z = (grp / (WW * HH)) * 2;

    const float4* fa = &g_ff[((size_t)(z * HH + y) * 4) * WW + x];
    float4 A0 = fa[0], A1 = fa[WW], A2 = fa[2 * WW], A3 = fa[3 * WW];
    const float4* fb = &g_ff[((size_t)((z + 1) * HH + y) * 4) * WW + x];
    float4 B0 = fb[0], B1 = fb[WW], B2 = fb[2 * WW], B3 = fb[3 * WW];

    Top5 tA, tB;
    top5_init(tA);
    top5_init(tB);

    // slab indices for this warp: pza = 2*sub, 2*sub+1  (absolute fm z = z+pza)
    {
        const int pza = 2 * sub;
        const int pA = pza * 49, pB = (pza - 1) * 49;
        if (sub == 0)
            run_slice<true, false>(z + pza, y, x, pA, pB, A0, A1, A2, A3, B0, B1, B2, B3, tA, tB);
        else
            run_slice<true, true>(z + pza, y, x, pA, pB, A0, A1, A2, A3, B0, B1, B2, B3, tA, tB);
    }
    {
        const int pza = 2 * sub + 1;
        const int pA = pza * 49, pB = (pza - 1) * 49;
        if (sub == 3)
            run_slice<false, true>(z + pza, y, x, pA, pB, A0, A1, A2, A3, B0, B1, B2, B3, tA, tB);
        else
            run_slice<true, true>(z + pza, y, x, pA, pB, A0, A1, A2, A3, B0, B1, B2, B3, tA, tB);
    }

    // publish partial lists (disjoint ascending p-ranges across subs)
    float* pv = &sv[0][lane][sub * 5];
    int*   pi = &si[0][lane][sub * 5];
    pv[0] = tA.v0; pv[1] = tA.v1; pv[2] = tA.v2; pv[3] = tA.v3; pv[4] = tA.v4;
    pi[0] = tA.p0; pi[1] = tA.p1; pi[2] = tA.p2; pi[3] = tA.p3; pi[4] = tA.p4;
    float* qv = &sv[1][lane][sub * 5];
    int*   qi = &si[1][lane][sub * 5];
    qv[0] = tB.v0; qv[1] = tB.v1; qv[2] = tB.v2; qv[3] = tB.v3; qv[4] = tB.v4;
    qi[0] = tB.p0; qi[1] = tB.p1; qi[2] = tB.p2; qi[3] = tB.p3; qi[4] = tB.p4;

    __syncthreads();

    if (sub == 0) merge_scatter(&sv[0][lane][0], &si[0][lane][0], out, z, y, x);
    if (sub == 1) merge_scatter(&sv[1][lane][0], &si[1][lane][0], out, z + 1, y, x);
}

// ---------------------------------------------------------------------------
extern "C" void kernel_launch(void* const* d_in, const int* in_sizes, int n_in,
                              void* d_out, int out_size) {
    (void)in_sizes; (void)n_in; (void)out_size;
    const float* feat_fix = (const float*)d_in[0];
    const float* feat_mov = (const float*)d_in[1];
    float* out = (float*)d_out;

    int t = 256;
    int pool_total = N_FF + N_FM;
    pool_kernel<<<(pool_total + t - 1) / t, t>>>(feat_fix, feat_mov, out);

    // 128 threads = 4 warps (window quarters) x 32 voxel-pairs; NGRP/32 = 1152
    corr_scatter_kernel<<<NGRP / 32, 128>>>(out);
}

// round 12
// speedup vs baseline: 1.7649x; 1.7649x over previous
#include <cuda_runtime.h>

#define CIN 16
#define DIN 64
#define HIN 96
#define WIN 96
#define DD 32
#define HH 48
#define WW 48
#define NVOX (DD*HH*WW)          /* 73728 */
#define RR 3
#define PD (DD+2*RR)             /* 38 */
#define PH (HH+2*RR)             /* 54 */
#define PW (WW+2*RR)             /* 54 */
#define FMS 64                   /* padded row stride (float4) for g_fm */

#define N_FF (4*NVOX)
#define N_FM (4*PD*PH*PW)

// Pooled features. g_ff: ((z*HH+y)*4+q)*WW + x. g_fm zero-padded by RR each
// side, row stride padded to 64 float4 (aligned rows, shift addressing).
__device__ float4 g_ff[(size_t)DD*HH*4*WW];
__device__ __align__(256) float4 g_fm[(size_t)PD*PH*4*FMS];

// ---------------------------------------------------------------------------
// Fused pooling (both tensors, one grid) + zeroing of the output buffer.
// ---------------------------------------------------------------------------
__global__ void pool_kernel(const float* __restrict__ ff_in,
                            const float* __restrict__ fm_in,
                            float* __restrict__ out) {
    int i = blockIdx.x * blockDim.x + threadIdx.x;
    if (i < 2 * NVOX) out[i] = 0.0f;             // init output (scatter target)
    if (i < N_FF) {
        int x = i % WW;
        int y = (i / WW) % HH;
        int z = (i / (WW * HH)) % DD;
        int q = i / NVOX;
        float s[4];
#pragma unroll
        for (int cc = 0; cc < 4; cc++) {
            int c = q * 4 + cc;
            const float* p = ff_in + (((size_t)c * DIN + 2 * z) * HIN + 2 * y) * WIN + 2 * x;
            float acc = 0.f;
#pragma unroll
            for (int dz = 0; dz < 2; dz++)
#pragma unroll
                for (int dy = 0; dy < 2; dy++) {
                    const float2 v = *(const float2*)(p + (size_t)dz * HIN * WIN + dy * WIN);
                    acc += v.x + v.y;
                }
            s[cc] = acc * 0.125f;
        }
        g_ff[((size_t)(z * HH + y) * 4 + q) * WW + x] = make_float4(s[0], s[1], s[2], s[3]);
    } else {
        int j = i - N_FF;
        if (j >= N_FM) return;
        int x = j % PW;
        int y = (j / PW) % PH;
        int z = (j / (PW * PH)) % PD;
        int q = j / (PD * PH * PW);
        int iz = z - RR, iy = y - RR, ix = x - RR;
        float s[4] = {0.f, 0.f, 0.f, 0.f};
        if (iz >= 0 && iz < DD && iy >= 0 && iy < HH && ix >= 0 && ix < WW) {
#pragma unroll
            for (int cc = 0; cc < 4; cc++) {
                int c = q * 4 + cc;
                const float* p = fm_in + (((size_t)c * DIN + 2 * iz) * HIN + 2 * iy) * WIN + 2 * ix;
                float acc = 0.f;
#pragma unroll
                for (int dz = 0; dz < 2; dz++)
#pragma unroll
                    for (int dy = 0; dy < 2; dy++) {
                        const float2 v = *(const float2*)(p + (size_t)dz * HIN * WIN + dy * WIN);
                        acc += v.x + v.y;
                    }
                s[cc] = acc * 0.125f;
            }
        }
        g_fm[((size_t)(z * PH + y) * 4 + q) * FMS + x] = make_float4(s[0], s[1], s[2], s[3]);
    }
}

// ---------------------------------------------------------------------------
// Top-5 insertion (strict > keeps earliest window index on ties -> lax.top_k)
// ---------------------------------------------------------------------------
#define DEF_TOPK(P)                                                           \
    float P##v0 = -1e30f, P##v1 = -1e30f, P##v2 = -1e30f, P##v3 = -1e30f,     \
          P##v4 = -1e30f;                                                     \
    int P##q0 = 0, P##q1 = 0, P##q2 = 0, P##q3 = 0, P##q4 = 0;

#define TOPK_INS(P, cval, pidx)                                               \
    if (cval > P##v4) {                                                       \
        P##v4 = cval; P##q4 = pidx;                                           \
        if (P##v4 > P##v3) { float t = P##v4; P##v4 = P##v3; P##v3 = t;       \
                             int u = P##q4; P##q4 = P##q3; P##q3 = u; }       \
        if (P##v3 > P##v2) { float t = P##v3; P##v3 = P##v2; P##v2 = t;       \
                             int u = P##q3; P##q3 = P##q2; P##q2 = u; }       \
        if (P##v2 > P##v1) { float t = P##v2; P##v2 = P##v1; P##v1 = t;       \
                             int u = P##q2; P##q2 = P##q1; P##q1 = u; }       \
        if (P##v1 > P##v0) { float t = P##v1; P##v1 = P##v0; P##v0 = t;       \
                             int u = P##q1; P##q1 = P##q0; P##q0 = u; }       \
    }

// dot of 16-ch fixed features with moving features, sequential channel order
// (must stay sequential: matches reference summation, rel_err ~9e-8)
__device__ __forceinline__ float dot16(const float4& a0, const float4& a1,
                                       const float4& a2, const float4& a3,
                                       const float4& m0, const float4& m1,
                                       const float4& m2, const float4& m3) {
    float c = a0.x * m0.x;
    c = fmaf(a0.y, m0.y, c); c = fmaf(a0.z, m0.z, c); c = fmaf(a0.w, m0.w, c);
    c = fmaf(a1.x, m1.x, c); c = fmaf(a1.y, m1.y, c);
    c = fmaf(a1.z, m1.z, c); c = fmaf(a1.w, m1.w, c);
    c = fmaf(a2.x, m2.x, c); c = fmaf(a2.y, m2.y, c);
    c = fmaf(a2.z, m2.z, c); c = fmaf(a2.w, m2.w, c);
    c = fmaf(a3.x, m3.x, c); c = fmaf(a3.y, m3.y, c);
    c = fmaf(a3.z, m3.z, c); c = fmaf(a3.w, m3.w, c);
    return c;
}

// ---------------------------------------------------------------------------
// scatter one top-k winner into both output levels
// ---------------------------------------------------------------------------
__device__ __forceinline__ void scatter_one(float* __restrict__ out,
                                            int z, int y, int x,
                                            float v, int pj) {
    const float sc[4] = {1.0f, 0.5f, 0.25f, 0.125f};
    int oz = pj / 49 - 3;
    int oy = (pj / 7) % 7 - 3;
    int ox = pj % 7 - 3;

    // level 0: integer displacement, single unit-weight corner
    {
        int tz = min(max(z + oz, 0), DD - 1);
        int ty = min(max(y + oy, 0), HH - 1);
        int tx = min(max(x + ox, 0), WW - 1);
        atomicAdd(&out[(tz * HH + ty) * WW + tx], v);
    }
    // level 1: displacement * 0.5, trilinear splat
    {
        int fz = oz >> 1, fy = oy >> 1, fx = ox >> 1;   // floor(o/2)
        int ez = oz & 1, ey = oy & 1, ex = ox & 1;      // odd -> two corners
        float wv = v * sc[ez + ey + ex];
        float* out1 = out + NVOX;
#pragma unroll
        for (int cz = 0; cz < 2; cz++) {
            if (cz > ez) break;
            int tz = min(max(z + fz + cz, 0), DD - 1);
#pragma unroll
            for (int cy = 0; cy < 2; cy++) {
                if (cy > ey) break;
                int ty = min(max(y + fy + cy, 0), HH - 1);
#pragma unroll
                for (int cx = 0; cx < 2; cx++) {
                    if (cx > ex) break;
                    int tx = min(max(x + fx + cx, 0), WW - 1);
                    atomicAdd(&out1[(tz * HH + ty) * WW + tx], wv);
                }
            }
        }
    }
}

// merge 4 partial top-5 lists (20 smem entries) -> global top-5, then scatter.
// Tie-break: equal values -> smaller flat window index p (matches lax.top_k;
// partial lists cover disjoint ascending p-ranges so ties resolve by p).
__device__ __forceinline__ void merge_scatter20(const float* __restrict__ sv,
                                                const int* __restrict__ si,
                                                float* __restrict__ out,
                                                int z, int y, int x) {
    unsigned used = 0;
#pragma unroll
    for (int k = 0; k < 5; k++) {
        float best = -3e38f;
        int bestp = 0x7fffffff;
        int bi = 0;
        for (int i = 0; i < 20; i++) {
            if (used & (1u << i)) continue;
            float v = sv[i];
            int p = si[i];
            if (v > best || (v == best && p < bestp)) { best = v; bestp = p; bi = i; }
        }
        used |= 1u << bi;
        scatter_one(out, z, y, x, best, bestp);
    }
}

// ---------------------------------------------------------------------------
// Correlation + top-5 + scatter.  ONE output voxel per thread (60 regs, no
// spills — R11 proved forcing regs below natural spills to local/L2), with
// the 49 (pz,py) window rows split 13/12/12/12 across the FOUR warps of the
// block (warp-uniform -> no divergence).  Doubling the split vs R9 doubles
// the total warp supply (9216 warps = 62/SM available vs 31), so residency
// reaches the ~34-warp register cap instead of R9's grid-capped 28, and wave
// quantization shrinks.  Lanes map to 32 consecutive x -> fully coalesced
// 512B row loads (unchanged from R9).  Four partial top-5 lists per voxel
// merge in shared memory.
// ---------------------------------------------------------------------------
__global__ void __launch_bounds__(128, 8) corr_scatter_kernel(float* __restrict__ out) {
    __shared__ float sv[32][20];
    __shared__ int   si[32][20];

    const int lane = threadIdx.x & 31;
    const int sub  = threadIdx.x >> 5;           // 0..3, warp-uniform
    const int grp  = blockIdx.x * 32 + lane;     // exact grid: no guard
    const int x = grp % WW;
    const int y = (grp / WW) % HH;
    const int z = grp / (WW * HH);

    const float4* fa = &g_ff[((size_t)(z * HH + y) * 4) * WW + x];
    float4 a0 = fa[0], a1 = fa[WW], a2 = fa[2 * WW], a3 = fa[3 * WW];

    DEF_TOPK(A)

    // row ranges per warp: 0-12 / 13-24 / 25-36 / 37-48  (13/12/12/12)
    const int r0 = (sub == 0) ? 0 : 13 + (sub - 1) * 12;
    const int r1 = (sub == 0) ? 13 : r0 + 12;
    for (int r = r0; r < r1; r++) {
        const int pz = r / 7;                    // const-div -> mul/shift
        const int py = r % 7;
        const float4* __restrict__ mb =
            &g_fm[((size_t)((z + pz) * PH + (y + py)) * 4) * FMS + x];
        const int rowp = r * 7;                  // p = pz*49 + py*7 + px
#pragma unroll
        for (int px = 0; px < 7; px++) {
            float4 m0 = mb[px];
            float4 m1 = mb[FMS + px];
            float4 m2 = mb[2 * FMS + px];
            float4 m3 = mb[3 * FMS + px];
            float c = dot16(a0, a1, a2, a3, m0, m1, m2, m3);
            TOPK_INS(A, c, rowp + px)
        }
    }

    // publish partial list (disjoint ascending p-ranges across subs)
    float* pv = &sv[lane][sub * 5];
    int*   pi = &si[lane][sub * 5];
    pv[0] = Av0; pv[1] = Av1; pv[2] = Av2; pv[3] = Av3; pv[4] = Av4;
    pi[0] = Aq0; pi[1] = Aq1; pi[2] = Aq2; pi[3] = Aq3; pi[4] = Aq4;

    __syncthreads();

    if (sub == 0)
        merge_scatter20(&sv[lane][0], &si[lane][0], out, z, y, x);
}

// ---------------------------------------------------------------------------
extern "C" void kernel_launch(void* const* d_in, const int* in_sizes, int n_in,
                              void* d_out, int out_size) {
    (void)in_sizes; (void)n_in; (void)out_size;
    const float* feat_fix = (const float*)d_in[0];
    const float* feat_mov = (const float*)d_in[1];
    float* out = (float*)d_out;

    int t = 256;
    int pool_total = N_FF + N_FM;
    pool_kernel<<<(pool_total + t - 1) / t, t>>>(feat_fix, feat_mov, out);

    // 128 threads = 4 warps (window quarters) x 32 voxels; NVOX/32 = 2304
    corr_scatter_kernel<<<NVOX / 32, 128>>>(out);
}